// round 16
// baseline (speedup 1.0000x reference)
#include <cuda_runtime.h>
#include <cuda_bf16.h>
#include <cstdint>

// Chunked-parallel scan of:  s = sigmoid(10*(s + (Wx+b)_t - 0.5)),  pred_t = x_t . s
// Run in t = 2s-1 domain:  t' = tanh(2.5 t + 5(Wx+b)),
// pred = 0.5*(x.t) + 0.5*(x0+x1+x2).  One MUFU.TANH per component per step.
//
// R16: chained windows AT occupancy. Each lane owns 64 consecutive steps
// (4 windows of 16); state chains across windows so warmup (16) runs once per
// 64 steps (1.25x amplification, steps -17% vs R11). Per-warp footprint is two
// 6.5KB buffers (window = 12 f4/lane, pitch 13); the warmup preamble borrows
// buffer 0. TPB=64, 26KB static smem -> 8 blocks/SM = 16 warp-slots; 1024
// blocks = single wave. Depth-1 rolling cp.async prefetch; window loop NOT
// unrolled (R15's 196-reg blowup). Warp-local sync only.

static constexpr int WSTEPS = 16;               // steps per window (12 f4/lane)
static constexpr int NW     = 4;                // windows per lane (64 steps)
static constexpr int WM     = 16;               // warmup steps (12 f4)
static constexpr int TPB    = 64;               // 2 warps per block
static constexpr int WPB    = TPB / 32;
static constexpr int BUFN   = 32 * 13;          // 416 f4 per buffer
static constexpr int SEGF4  = WSTEPS * NW * 3 / 4;     // 48 f4 per lane span
static constexpr int WARPF4 = 32 * SEGF4;       // 1536 f4 per warp span

__device__ __forceinline__ float tanhapx(float z) {
    float r; asm("tanh.approx.f32 %0, %1;" : "=f"(r) : "f"(z)); return r;
}
__device__ __forceinline__ void cp16(unsigned int dst, const void* src) {
    asm volatile("cp.async.cg.shared.global [%0], [%1], 16;" :: "r"(dst), "l"(src));
}

__global__ void __launch_bounds__(TPB, 8)
updater_kernel(const float* __restrict__ x,
               const float* __restrict__ Wg,
               const float* __restrict__ bg,
               const float* __restrict__ net0,
               float* __restrict__ out)
{
    __shared__ float4 sm[WPB * 2 * BUFN];       // 26624 B static

    const int lane = threadIdx.x & 31;
    const int wid  = threadIdx.x >> 5;
    const long wb  = (long)blockIdx.x * WPB + wid;      // global warp id (0..2047)
    const bool first = (wb == 0) && (lane == 0);

    // u5 = 5*(W x + b)
    const float W00 = 5.f*Wg[0], W01 = 5.f*Wg[1], W02 = 5.f*Wg[2];
    const float W10 = 5.f*Wg[3], W11 = 5.f*Wg[4], W12 = 5.f*Wg[5];
    const float W20 = 5.f*Wg[6], W21 = 5.f*Wg[7], W22 = 5.f*Wg[8];
    const float c0 = 5.f*bg[0], c1 = 5.f*bg[1], c2 = 5.f*bg[2];

    const float4* __restrict__ xf4 = reinterpret_cast<const float4*>(x);
    float4* __restrict__ of4 = reinterpret_cast<float4*>(out);

    float4* bufs = sm + wid * (2 * BUFN);       // this warp's two buffers
    const unsigned int sbase = (unsigned int)__cvta_generic_to_shared(bufs);
    const long gbase = wb * WARPF4;             // warp span start (f4)

    // ---- G0: warmup preamble into buffer 0 (12 f4 ending at each lane's start) ----
    #pragma unroll
    for (int l = 0; l < 12; ++l) {
        int i = lane + 32 * l;                  // 0..383
        int seg = i / 12, off = i - seg * 12;
        long g = gbase + (long)seg * SEGF4 - 12 + off;
        if (g < 0) g = 0;                       // only warp 0 lane 0 (discarded)
        cp16(sbase + (unsigned int)(seg * 13 + off) * 16u, xf4 + g);
    }
    asm volatile("cp.async.commit_group;");

    // ---- window issue: win wi -> buffer ((wi+1)&1) ----
    auto issue_win = [&](int wi) {
        unsigned int dbuf = sbase + (unsigned int)(((wi + 1) & 1) * BUFN) * 16u;
        #pragma unroll
        for (int l = 0; l < 12; ++l) {
            int i = lane + 32 * l;
            int seg = i / 12, off = i - seg * 12;
            cp16(dbuf + (unsigned int)(seg * 13 + off) * 16u,
                 xf4 + gbase + (long)seg * SEGF4 + wi * 12 + off);
        }
        asm volatile("cp.async.commit_group;");
    };

    issue_win(0);                               // -> buffer 1

    float t0 = 0.f, t1 = 0.f, t2 = 0.f;         // midpoint seed (s = 0.5)

    // ---- warmup: 16 steps from buffer 0 (win0 still in flight) ----
    asm volatile("cp.async.wait_group 1;");
    __syncwarp();
    {
        const float4* myw = bufs + lane * 13;
        #pragma unroll
        for (int g = 0; g < WM / 4; ++g) {
            float4 p = myw[3*g], q = myw[3*g+1], r = myw[3*g+2];
            auto wstep = [&](float X0, float X1, float X2) {
                float u0 = fmaf(W00, X0, fmaf(W01, X1, fmaf(W02, X2, c0)));
                float u1 = fmaf(W10, X0, fmaf(W11, X1, fmaf(W12, X2, c1)));
                float u2 = fmaf(W20, X0, fmaf(W21, X1, fmaf(W22, X2, c2)));
                t0 = tanhapx(fmaf(2.5f, t0, u0));
                t1 = tanhapx(fmaf(2.5f, t1, u1));
                t2 = tanhapx(fmaf(2.5f, t2, u2));
            };
            wstep(p.x, p.y, p.z);
            wstep(p.w, q.x, q.y);
            wstep(q.z, q.w, r.x);
            wstep(r.y, r.z, r.w);
        }
    }
    if (first) {
        t0 = fmaf(2.f, net0[0], -1.f);
        t1 = fmaf(2.f, net0[1], -1.f);
        t2 = fmaf(2.f, net0[2], -1.f);
    }

    auto mstep = [&](float X0, float X1, float X2) -> float {
        float u0 = fmaf(W00, X0, fmaf(W01, X1, fmaf(W02, X2, c0)));
        float u1 = fmaf(W10, X0, fmaf(W11, X1, fmaf(W12, X2, c1)));
        float u2 = fmaf(W20, X0, fmaf(W21, X1, fmaf(W22, X2, c2)));
        t0 = tanhapx(fmaf(2.5f, t0, u0));
        t1 = tanhapx(fmaf(2.5f, t1, u1));
        t2 = tanhapx(fmaf(2.5f, t2, u2));
        float h = fmaf(0.5f, X2, fmaf(0.5f, X1, 0.5f * X0));
        float d = fmaf(X0, t0, fmaf(X1, t1, X2 * t2));
        return fmaf(0.5f, d, h);
    };

    // ---- chained window loop (NOT unrolled: keeps regs/I-cache small) ----
    #pragma unroll 1
    for (int wi = 0; wi < NW; ++wi) {
        if (wi + 1 < NW) {
            issue_win(wi + 1);                  // -> buffer (wi&1); prior contents consumed
            asm volatile("cp.async.wait_group 1;");
        } else {
            asm volatile("cp.async.wait_group 0;");
        }
        __syncwarp();

        float4* buf = bufs + ((wi + 1) & 1) * BUFN;
        float4* my  = buf + lane * 13;

        #pragma unroll
        for (int g = 0; g < 4; ++g) {           // 16 steps
            float4 p = my[3*g], q = my[3*g+1], r = my[3*g+2];
            float4 res;
            res.x = mstep(p.x, p.y, p.z);
            res.y = mstep(p.w, q.x, q.y);
            res.z = mstep(q.z, q.w, r.x);
            res.w = mstep(r.y, r.z, r.w);
            my[g] = res;                        // stash in consumed slot (g <= 3g)
        }
        __syncwarp();                           // all lanes' preds visible

        // coalesced store: 128 f4 per window per warp
        #pragma unroll
        for (int l = 0; l < 4; ++l) {
            int i = lane + 32 * l;              // 0..127
            int seg = i >> 2, off = i & 3;
            of4[wb * 512 + seg * 16 + wi * 4 + off] = buf[seg * 13 + off];
        }
        // no extra sync: warp-lockstep issue orders these LDS/STG before the
        // next iteration's cp.async; async data lands >= DRAM latency later
    }
}

extern "C" void kernel_launch(void* const* d_in, const int* in_sizes, int n_in,
                              void* d_out, int out_size)
{
    const float* x    = (const float*)d_in[0];
    const float* W    = (const float*)d_in[1];
    const float* b    = (const float*)d_in[2];
    const float* net0 = (const float*)d_in[3];
    float* out = (float*)d_out;

    int n      = in_sizes[0] / 3;               // B = 4194304
    int nwarps = n / (32 * WSTEPS * NW);        // 2048
    int blocks = nwarps / WPB;                  // 1024
    updater_kernel<<<blocks, TPB>>>(x, W, b, net0, out);
}